// round 3
// baseline (speedup 1.0000x reference)
#include <cuda_runtime.h>
#include <cuda_bf16.h>
#include <cooperative_groups.h>
#include <cstdint>
#include <cstddef>

namespace cg = cooperative_groups;

// Problem dims
#define Vv 32000
#define Ee 300
#define Hh 300
#define G4 1200   // 4*H
#define Bb 128
#define Tt 512
#define Oo 9

// ---------------- scratch (device globals: allocation-free rule) ----------------
// proj[dir][v][1200] = emb_table @ W_ih^T + b   (fp32)
__device__ float g_proj[2ull * Vv * G4];          // 307.2 MB
// h[dir][b][t][300]
__device__ float g_h[2ull * Bb * Tt * Hh];        // 157.3 MB

// =================================================================
// K1: vocab projection GEMM  C[v][n] = sum_k emb[v][k] * W[n][k] + bias[n]
// M = 32000, N = 1200, K = 300.  BM=128, BN=64, BK=16, 256 thr, 8x4 micro.
// =================================================================
#define K1_BM 128
#define K1_BN 64
#define K1_BK 16

__global__ void proj_kernel(const float* __restrict__ emb,
                            const float* __restrict__ Wf,
                            const float* __restrict__ Wb,
                            const float* __restrict__ bf,
                            const float* __restrict__ bb) {
    __shared__ float As[K1_BK][K1_BM + 4];
    __shared__ float Bs[K1_BK][K1_BN + 4];

    const int dir = blockIdx.z;
    const float* __restrict__ W    = dir ? Wb : Wf;
    const float* __restrict__ bias = dir ? bb : bf;
    const int n0 = blockIdx.x * K1_BN;
    const int m0 = blockIdx.y * K1_BM;
    const int tid = threadIdx.x;
    const int tx = tid & 15;       // N dim (16 * 4 = 64)
    const int ty = tid >> 4;       // M dim (16 * 8 = 128)

    float acc[8][4];
#pragma unroll
    for (int i = 0; i < 8; i++)
#pragma unroll
        for (int j = 0; j < 4; j++) acc[i][j] = 0.f;

    for (int kk = 0; kk < Ee; kk += K1_BK) {
        // ---- load A tile (emb rows), 2 float4 per thread ----
#pragma unroll
        for (int it = 0; it < 2; it++) {
            int f = tid + it * 256;
            int row = f >> 2;
            int kq  = (f & 3) * 4;
            int k0  = kk + kq;
            const float* src = emb + (size_t)(m0 + row) * Ee;
            float4 v;
            if (k0 + 3 < Ee) {
                v = *(const float4*)(src + k0);
            } else {
                v.x = (k0 + 0 < Ee) ? src[k0 + 0] : 0.f;
                v.y = (k0 + 1 < Ee) ? src[k0 + 1] : 0.f;
                v.z = (k0 + 2 < Ee) ? src[k0 + 2] : 0.f;
                v.w = (k0 + 3 < Ee) ? src[k0 + 3] : 0.f;
            }
            As[kq + 0][row] = v.x; As[kq + 1][row] = v.y;
            As[kq + 2][row] = v.z; As[kq + 3][row] = v.w;
        }
        // ---- load B tile (W_ih rows), 1 float4 per thread ----
        {
            int f = tid;
            int row = f >> 2;
            int kq  = (f & 3) * 4;
            int k0  = kk + kq;
            int n   = n0 + row;
            float4 v = make_float4(0.f, 0.f, 0.f, 0.f);
            if (n < G4) {
                const float* src = W + (size_t)n * Ee;
                if (k0 + 3 < Ee) {
                    v = *(const float4*)(src + k0);
                } else {
                    v.x = (k0 + 0 < Ee) ? src[k0 + 0] : 0.f;
                    v.y = (k0 + 1 < Ee) ? src[k0 + 1] : 0.f;
                    v.z = (k0 + 2 < Ee) ? src[k0 + 2] : 0.f;
                    v.w = (k0 + 3 < Ee) ? src[k0 + 3] : 0.f;
                }
            }
            Bs[kq + 0][row] = v.x; Bs[kq + 1][row] = v.y;
            Bs[kq + 2][row] = v.z; Bs[kq + 3][row] = v.w;
        }
        __syncthreads();

#pragma unroll
        for (int k = 0; k < K1_BK; k++) {
            float4 a0 = *(float4*)&As[k][ty * 8];
            float4 a1 = *(float4*)&As[k][ty * 8 + 4];
            float4 bv = *(float4*)&Bs[k][tx * 4];
            float av[8] = {a0.x, a0.y, a0.z, a0.w, a1.x, a1.y, a1.z, a1.w};
            float bvv[4] = {bv.x, bv.y, bv.z, bv.w};
#pragma unroll
            for (int i = 0; i < 8; i++)
#pragma unroll
                for (int j = 0; j < 4; j++) acc[i][j] += av[i] * bvv[j];
        }
        __syncthreads();
    }

    // ---- store with bias ----
    float* cbase = g_proj + (size_t)dir * Vv * G4;
#pragma unroll
    for (int i = 0; i < 8; i++) {
        int m = m0 + ty * 8 + i;
#pragma unroll
        for (int j = 0; j < 4; j++) {
            int n = n0 + tx * 4 + j;
            if (n < G4) cbase[(size_t)m * G4 + n] = acc[i][j] + bias[n];
        }
    }
}

// =================================================================
// K2: BiLSTM recurrence. Cluster of 8 CTAs = (dir, 16 batch rows).
// CTA rank r owns hidden slice [r*40, r*40+40)  (300 total, last CTA 20 valid).
// SMEM: W_s[300][160] fp32 (weight-stationary slice, 192 KB)
//       h_s[320][16] fp32 (full h replicated per CTA, k-major, 20.5 KB)
// threads = 160: thread = (rowgroup rg in 0..3 [4 batch rows], hidden j in 0..39)
// =================================================================
#define REC_THREADS 160
#define REC_SMEM (300 * 160 * 4 + 320 * 16 * 4)   // 212480 B

__device__ __forceinline__ float sigmoidf_(float x) {
    return 1.0f / (1.0f + __expf(-x));
}
__device__ __forceinline__ float tanhf_(float x) {
    float xx = fminf(fmaxf(x, -15.f), 15.f);
    float e = __expf(-2.0f * xx);
    return (1.0f - e) / (1.0f + e);
}

__global__ void __cluster_dims__(8, 1, 1)
lstm_rec_kernel(const int* __restrict__ x,
                const float* __restrict__ Whh_f,
                const float* __restrict__ Whh_b) {
    extern __shared__ float sm[];
    float* W_s = sm;                 // [k 0..299][gi 0..159], gi = g*40 + j
    float* h_s = sm + 300 * 160;     // [k 0..319][row 0..15]

    cg::cluster_group cluster = cg::this_cluster();

    const int bx   = blockIdx.x;
    const int cid  = bx >> 3;           // 0..15
    const int rank = bx & 7;            // 0..7
    const int dir  = cid >> 3;          // 0,1
    const int bg   = cid & 7;           // 0..7
    const int b0   = bg * 16;
    const int h0   = rank * 40;
    const int tid  = threadIdx.x;
    const int j    = tid % 40;
    const int rg   = tid / 40;          // 0..3
    const bool validh = (h0 + j) < Hh;
    const int hjc = validh ? (h0 + j) : (Hh - 1);

    const float* __restrict__ Whh = dir ? Whh_b : Whh_f;

    // ---- load weight slice into SMEM (transposed to [k][gate]) ----
    {
        int gi = tid;                    // 0..159
        int g  = gi / 40;
        int jj = gi % 40;
        bool v = (h0 + jj) < Hh;
        const float* wrow = Whh + (size_t)(g * Hh + (v ? (h0 + jj) : 0)) * Hh;
        for (int k4 = 0; k4 < Hh; k4 += 4) {
            float4 w = v ? *(const float4*)(wrow + k4) : make_float4(0.f, 0.f, 0.f, 0.f);
            W_s[(k4 + 0) * 160 + gi] = w.x;
            W_s[(k4 + 1) * 160 + gi] = w.y;
            W_s[(k4 + 2) * 160 + gi] = w.z;
            W_s[(k4 + 3) * 160 + gi] = w.w;
        }
    }
    // ---- zero h ----
    for (int i = tid; i < 320 * 16; i += REC_THREADS) h_s[i] = 0.f;
    __syncthreads();

    const int* xr0 = x + (size_t)(b0 + rg * 4 + 0) * Tt;
    const int* xr1 = x + (size_t)(b0 + rg * 4 + 1) * Tt;
    const int* xr2 = x + (size_t)(b0 + rg * 4 + 2) * Tt;
    const int* xr3 = x + (size_t)(b0 + rg * 4 + 3) * Tt;
    const float* ptab = g_proj + (size_t)dir * Vv * G4;

    float c0 = 0.f, c1 = 0.f, c2 = 0.f, c3 = 0.f;

    for (int ti = 0; ti < Tt; ti++) {
        const int tcur = dir ? (Tt - 1 - ti) : ti;

        // gather pre-projected inputs for this step (i,f,g,o for 4 rows)
        const float* p0 = ptab + (size_t)xr0[tcur] * G4 + hjc;
        const float* p1 = ptab + (size_t)xr1[tcur] * G4 + hjc;
        const float* p2 = ptab + (size_t)xr2[tcur] * G4 + hjc;
        const float* p3 = ptab + (size_t)xr3[tcur] * G4 + hjc;
        float xp[16];
#pragma unroll
        for (int g = 0; g < 4; g++) {
            xp[0 * 4 + g] = p0[g * Hh];
            xp[1 * 4 + g] = p1[g * Hh];
            xp[2 * 4 + g] = p2[g * Hh];
            xp[3 * 4 + g] = p3[g * Hh];
        }

        // ---- gate dots: acc[r][g] = sum_k h[r][k] * W[g*40+j][k] ----
        float acc[16];
#pragma unroll
        for (int i = 0; i < 16; i++) acc[i] = 0.f;

        const float* hp = h_s + rg * 4;
        const float* wp = W_s + j;
#pragma unroll 4
        for (int k = 0; k < Hh; k++) {
            float4 hv = *(const float4*)(hp + k * 16);
            float wi = wp[k * 160 + 0];
            float wf = wp[k * 160 + 40];
            float wg = wp[k * 160 + 80];
            float wo = wp[k * 160 + 120];
            acc[0]  += hv.x * wi; acc[1]  += hv.x * wf; acc[2]  += hv.x * wg; acc[3]  += hv.x * wo;
            acc[4]  += hv.y * wi; acc[5]  += hv.y * wf; acc[6]  += hv.y * wg; acc[7]  += hv.y * wo;
            acc[8]  += hv.z * wi; acc[9]  += hv.z * wf; acc[10] += hv.z * wg; acc[11] += hv.z * wo;
            acc[12] += hv.w * wi; acc[13] += hv.w * wf; acc[14] += hv.w * wg; acc[15] += hv.w * wo;
        }

        // ---- LSTM cell update (c in registers) ----
        float hn[4];
        {
            float gi_, gf_, gg_, go_, tg;
            gi_ = acc[0] + xp[0];  gf_ = acc[1] + xp[1];  gg_ = acc[2] + xp[2];  go_ = acc[3] + xp[3];
            tg = tanhf_(gg_); c0 = sigmoidf_(gf_) * c0 + sigmoidf_(gi_) * tg; hn[0] = sigmoidf_(go_) * tanhf_(c0);
            gi_ = acc[4] + xp[4];  gf_ = acc[5] + xp[5];  gg_ = acc[6] + xp[6];  go_ = acc[7] + xp[7];
            tg = tanhf_(gg_); c1 = sigmoidf_(gf_) * c1 + sigmoidf_(gi_) * tg; hn[1] = sigmoidf_(go_) * tanhf_(c1);
            gi_ = acc[8] + xp[8];  gf_ = acc[9] + xp[9];  gg_ = acc[10] + xp[10]; go_ = acc[11] + xp[11];
            tg = tanhf_(gg_); c2 = sigmoidf_(gf_) * c2 + sigmoidf_(gi_) * tg; hn[2] = sigmoidf_(go_) * tanhf_(c2);
            gi_ = acc[12] + xp[12]; gf_ = acc[13] + xp[13]; gg_ = acc[14] + xp[14]; go_ = acc[15] + xp[15];
            tg = tanhf_(gg_); c3 = sigmoidf_(gf_) * c3 + sigmoidf_(gi_) * tg; hn[3] = sigmoidf_(go_) * tanhf_(c3);
        }

        cluster.sync();   // everyone finished reading h_s of step t-1

        // ---- replicate new h to all 8 CTAs' h buffers (DSMEM push) ----
        {
            float4 hv4 = make_float4(hn[0], hn[1], hn[2], hn[3]);
            unsigned off = (unsigned)((h0 + j) * 16 + rg * 4);
#pragma unroll
            for (int rr = 0; rr < 8; rr++) {
                float* ph = cluster.map_shared_rank(h_s, rr);
                *(float4*)(ph + off) = hv4;
            }
        }

        cluster.sync();   // h_s complete for step t

        // ---- write h to global for the output stage ----
        if (validh) {
            size_t base = ((size_t)(dir * Bb + b0 + rg * 4) * Tt + tcur) * Hh + (h0 + j);
            const size_t strideB = (size_t)Tt * Hh;
            g_h[base + 0 * strideB] = hn[0];
            g_h[base + 1 * strideB] = hn[1];
            g_h[base + 2 * strideB] = hn[2];
            g_h[base + 3 * strideB] = hn[3];
        }
    }
}

// =================================================================
// K3: output linear + softmax. One warp per (b,t).
// =================================================================
__global__ void out_kernel(const float* __restrict__ W_lin,
                           const float* __restrict__ b_lin,
                           float* __restrict__ out) {
    const int warp = (blockIdx.x * blockDim.x + threadIdx.x) >> 5;
    const int lane = threadIdx.x & 31;
    if (warp >= Bb * Tt) return;
    const int b = warp / Tt;
    const int t = warp % Tt;

    const float* hf = g_h + ((size_t)(0 * Bb + b) * Tt + t) * Hh;
    const float* hb = g_h + ((size_t)(1 * Bb + b) * Tt + t) * Hh;

    float acc[Oo];
#pragma unroll
    for (int o = 0; o < Oo; o++) acc[o] = 0.f;

    for (int k = lane; k < Hh; k += 32) {
        float a = hf[k];
        float c = hb[k];
#pragma unroll
        for (int o = 0; o < Oo; o++)
            acc[o] += a * W_lin[o * (2 * Hh) + k] + c * W_lin[o * (2 * Hh) + Hh + k];
    }
#pragma unroll
    for (int o = 0; o < Oo; o++) {
#pragma unroll
        for (int off = 16; off > 0; off >>= 1)
            acc[o] += __shfl_xor_sync(0xFFFFFFFFu, acc[o], off);
        acc[o] += b_lin[o];
    }
    // softmax over 9 (all lanes have identical values)
    float mx = acc[0];
#pragma unroll
    for (int o = 1; o < Oo; o++) mx = fmaxf(mx, acc[o]);
    float s = 0.f;
    float e[Oo];
#pragma unroll
    for (int o = 0; o < Oo; o++) { e[o] = __expf(acc[o] - mx); s += e[o]; }
    float inv = 1.0f / s;
    if (lane < Oo) out[(size_t)warp * Oo + lane] = e[lane] * inv;
}

// =================================================================
// launcher
// =================================================================
extern "C" void kernel_launch(void* const* d_in, const int* in_sizes, int n_in,
                              void* d_out, int out_size) {
    const int*   x     = (const int*)  d_in[0];
    const float* emb   = (const float*)d_in[1];
    const float* Wih_f = (const float*)d_in[2];
    const float* Whh_f = (const float*)d_in[3];
    const float* b_f   = (const float*)d_in[4];
    const float* Wih_b = (const float*)d_in[5];
    const float* Whh_b = (const float*)d_in[6];
    const float* b_b   = (const float*)d_in[7];
    const float* W_lin = (const float*)d_in[8];
    const float* b_lin = (const float*)d_in[9];
    float* out = (float*)d_out;

    cudaFuncSetAttribute(lstm_rec_kernel,
                         cudaFuncAttributeMaxDynamicSharedMemorySize, REC_SMEM);

    // K1: vocab projection. grid = (N tiles, M tiles, dir)
    {
        dim3 grid((G4 + K1_BN - 1) / K1_BN, Vv / K1_BM, 2);
        proj_kernel<<<grid, 256>>>(emb, Wih_f, Wih_b, b_f, b_b);
    }
    // K2: recurrence. 128 CTAs, clusters of 8.
    lstm_rec_kernel<<<128, REC_THREADS, REC_SMEM>>>(x, Whh_f, Whh_b);

    // K3: output. 65536 warps.
    {
        int warps_per_block = 8;
        int blocks = (Bb * Tt) / warps_per_block;
        out_kernel<<<blocks, warps_per_block * 32>>>(W_lin, b_lin, out);
    }
}